// round 14
// baseline (speedup 1.0000x reference)
#include <cuda_runtime.h>
#include <cuda_fp16.h>
#include <cstdint>

// ---------------- problem constants ----------------------------------------
#define TREES   512
#define TSIZE   400
#define NNODES  (TREES * TSIZE)   // 204800
#define INFEAT  768
#define HFEAT   256
#define G3      768

// level geometry (ternary tree, 400 nodes):
//  d:      0    1    2    3     4     5      6
//  cnt:    1    3    9    27    81    243    36
//  start:  0    1    4    13    40    121    364
//  level-major row offsets: 0 512 2048 6656 20480 61952 186368  (end 204800)
//  parents for level d = first PC[d] locals of level d-1; PC: 1 3 9 27 81 12
//  children of parent local lp: 3*lp + k, k=0..2
//  leaves: level-5 locals 12..242 + all level-6
//
// GATE-INTERLEAVED column layout (applies to W_ih/W_hh rows, biases, gx cols):
//   pcol(g, j) = (j/8)*24 + g*8 + (j%8),  g in {r=0,z=1,n=2}, j in [0,256)
//   -> any aligned 24-col group = complete (r,z,n) triples for 8 h-cols.

// ---------------- scratch (device bss) ---------------------------------------
__device__ __half g_gx16[(size_t)NNODES * G3];         // input gates fp16, level-major, interleaved cols
__device__ float  g_h32 [(size_t)NNODES * HFEAT];      // hiddens fp32, level-major
__device__ __half g_h16 [(size_t)NNODES * HFEAT];      // hiddens fp16 (parents only)
__device__ __half g_x16 [(size_t)NNODES * INFEAT];     // fp16 inputs (node-major)
__device__ __half g_wih [3 * HFEAT * INFEAT];          // fp16 W_ih, rows permuted
__device__ __half g_whh [3 * HFEAT * HFEAT];           // fp16 W_hh, rows permuted
__device__ float  g_bihp[G3];                          // permuted b_ih
__device__ float  g_bhhp[G3];                          // permuted b_hh

// level-major row -> node row (node = tree*400 + s)
__device__ __forceinline__ int lm2node(int r) {
    int o, c, s0;
    if (r < 20480) {
        if (r < 2048) { if (r < 512) { o = 0;     c = 1;  s0 = 0;  }
                        else         { o = 512;   c = 3;  s0 = 1;  } }
        else          { if (r < 6656){ o = 2048;  c = 9;  s0 = 4;  }
                        else         { o = 6656;  c = 27; s0 = 13; } }
    } else {
        if (r < 186368){ if (r < 61952){ o = 20480; c = 81;  s0 = 40;  }
                         else          { o = 61952; c = 243; s0 = 121; } }
        else           { o = 186368; c = 36; s0 = 364; }
    }
    int t = (r - o) / c;
    int ls = (r - o) - t * c;
    return t * TSIZE + s0 + ls;
}

// ---------------- PTX helpers ------------------------------------------------
__device__ __forceinline__ void mma_f16(float* c, const uint32_t* a, const uint32_t* b) {
    asm volatile(
        "mma.sync.aligned.m16n8k16.row.col.f32.f16.f16.f32 "
        "{%0,%1,%2,%3}, {%4,%5,%6,%7}, {%8,%9}, {%0,%1,%2,%3};"
        : "+f"(c[0]), "+f"(c[1]), "+f"(c[2]), "+f"(c[3])
        : "r"(a[0]), "r"(a[1]), "r"(a[2]), "r"(a[3]), "r"(b[0]), "r"(b[1]));
}
__device__ __forceinline__ void ldsm4(uint32_t* r, uint32_t saddr) {
    asm volatile("ldmatrix.sync.aligned.m8n8.x4.shared.b16 {%0,%1,%2,%3}, [%4];"
        : "=r"(r[0]), "=r"(r[1]), "=r"(r[2]), "=r"(r[3]) : "r"(saddr));
}
__device__ __forceinline__ void cp16(uint32_t saddr, const void* g) {
    asm volatile("cp.async.cg.shared.global [%0], [%1], 16;" :: "r"(saddr), "l"(g));
}
__device__ __forceinline__ void cp_commit() { asm volatile("cp.async.commit_group;"); }
template <int N> __device__ __forceinline__ void cp_wait() {
    asm volatile("cp.async.wait_group %0;" :: "n"(N));
}

// fast accurate sigmoid/tanh: ex2.approx + rcp.approx (~1e-6 rel err)
__device__ __forceinline__ float sigx(float x) {
    float e, r;
    asm("ex2.approx.f32 %0, %1;" : "=f"(e) : "f"(-x * 1.4426950408889634f));
    asm("rcp.approx.f32 %0, %1;" : "=f"(r) : "f"(1.0f + e));
    return r;
}
__device__ __forceinline__ float tanhx(float x) {
    float e, r;
    asm("ex2.approx.f32 %0, %1;" : "=f"(e) : "f"(-x * 2.8853900817779268f));
    asm("rcp.approx.f32 %0, %1;" : "=f"(r) : "f"(1.0f + e));
    return __fmaf_rn(2.0f, r, -1.0f);
}

// ================= gx GEMM (R8 config, unchanged mainloop) ====================
#define BM 128
#define BN 128
#define BK 64
#define NS 3
#define BKP 72
#define A_STAGE_B (BM * BKP * 2)                 // 18432
#define B_STAGE_B (BN * BKP * 2)                 // 18432
#define STAGE_B   (A_STAGE_B + B_STAGE_B)        // 36864
#define SMEM_GX   (NS * STAGE_B)                 // 110592
#define NTHR 256

__global__ void __launch_bounds__(NTHR, 2)
gemm_gx(const __half* __restrict__ A, const __half* __restrict__ B,
        const float* __restrict__ bias, __half* __restrict__ C)
{
    extern __shared__ char smem[];
    const uint32_t sbase = (uint32_t)__cvta_generic_to_shared(smem);
    const int tid  = threadIdx.x;
    const int lane = tid & 31, warp = tid >> 5;
    const int wm = (warp >> 2) * 64;
    const int wn = (warp & 3) * 32;
    const int col0 = blockIdx.x * BN;
    const int row0 = blockIdx.y * BM;
    const int KT = INFEAT / BK;                  // 12

    const __half* asrc[4]; uint32_t adst[4];
    #pragma unroll
    for (int i = 0; i < 4; ++i) {
        int lin = tid + i * NTHR, r = lin >> 3, cc = lin & 7;
        int gr = lm2node(row0 + r);
        asrc[i] = A + (size_t)gr * INFEAT + cc * 8;
        adst[i] = (uint32_t)((r * BKP + cc * 8) * 2);
    }
    const __half* bsrc[4]; uint32_t bdst[4];
    #pragma unroll
    for (int i = 0; i < 4; ++i) {
        int lin = tid + i * NTHR, r = lin >> 3, cc = lin & 7;
        bsrc[i] = B + (size_t)(col0 + r) * INFEAT + cc * 8;
        bdst[i] = (uint32_t)((r * BKP + cc * 8) * 2);
    }
    auto issue = [&](int kt) {
        uint32_t sa = sbase + (uint32_t)(kt % NS) * STAGE_B;
        uint32_t sb = sa + A_STAGE_B;
        const int ko = kt * BK;
        #pragma unroll
        for (int i = 0; i < 4; ++i) cp16(sa + adst[i], asrc[i] + ko);
        #pragma unroll
        for (int i = 0; i < 4; ++i) cp16(sb + bdst[i], bsrc[i] + ko);
    };

    const int j = lane >> 3, sub = lane & 7;
    uint32_t aoff[4], boff[2];
    #pragma unroll
    for (int mi = 0; mi < 4; ++mi) {
        int arow = wm + mi * 16 + (j & 1) * 8 + sub;
        aoff[mi] = (uint32_t)(arow * BKP * 2 + (j >> 1) * 16);
    }
    #pragma unroll
    for (int p = 0; p < 2; ++p) {
        int brow = wn + p * 16 + ((lane >> 4) & 1) * 8 + sub;
        boff[p] = (uint32_t)(brow * BKP * 2 + ((lane >> 3) & 1) * 16);
    }

    float acc[4][4][4];
    #pragma unroll
    for (int mi = 0; mi < 4; ++mi)
        #pragma unroll
        for (int ni = 0; ni < 4; ++ni)
            #pragma unroll
            for (int v = 0; v < 4; ++v) acc[mi][ni][v] = 0.f;

    #pragma unroll
    for (int s = 0; s < NS - 1; ++s) { issue(s); cp_commit(); }

    for (int kt = 0; kt < KT; ++kt) {
        cp_wait<NS - 2>();
        __syncthreads();
        int nk = kt + NS - 1;
        if (nk < KT) issue(nk);
        cp_commit();

        uint32_t sA = sbase + (uint32_t)(kt % NS) * STAGE_B;
        uint32_t sB = sA + A_STAGE_B;
        #pragma unroll
        for (int kk = 0; kk < BK / 16; ++kk) {
            const uint32_t kb = kk * 32;
            uint32_t afr[4][4], bfr[2][4];
            #pragma unroll
            for (int mi = 0; mi < 4; ++mi) ldsm4(afr[mi], sA + aoff[mi] + kb);
            #pragma unroll
            for (int p = 0; p < 2; ++p)   ldsm4(bfr[p], sB + boff[p] + kb);
            #pragma unroll
            for (int mi = 0; mi < 4; ++mi) {
                #pragma unroll
                for (int p = 0; p < 2; ++p) {
                    mma_f16(acc[mi][2 * p],     afr[mi], &bfr[p][0]);
                    mma_f16(acc[mi][2 * p + 1], afr[mi], &bfr[p][2]);
                }
            }
        }
        __syncthreads();
    }

    const int g = lane >> 2, tig = lane & 3;
    #pragma unroll
    for (int mi = 0; mi < 4; ++mi) {
        int row = row0 + wm + mi * 16 + g;
        #pragma unroll
        for (int ni = 0; ni < 4; ++ni) {
            int col = col0 + wn + ni * 8 + 2 * tig;
            float b0 = bias[col], b1 = bias[col + 1];
            *(__half2*)(C + (size_t)row * G3 + col) =
                __floats2half2_rn(acc[mi][ni][0] + b0, acc[mi][ni][1] + b1);
            *(__half2*)(C + (size_t)(row + 8) * G3 + col) =
                __floats2half2_rn(acc[mi][ni][2] + b0, acc[mi][ni][3] + b1);
        }
    }
}

// ============ fused gh-GEMM + GRU (BN=192, gate-interleaved) ==================
// grid (4, PC*TREES/128). A = parent h16 rows; B = permuted W_hh.
// Epilogue: each thread holds (r,z,n) triples in acc; applies GRU to 3 children.
#define FBN 192
#define FB_STAGE (FBN * BKP * 2)                 // 27648
#define FSTAGE   (A_STAGE_B + FB_STAGE)          // 46080
#define SMEM_FU  (NS * FSTAGE)                   // 138240

__global__ void __launch_bounds__(256, 1)
gru_fused(const __half* __restrict__ Whh, const float* __restrict__ bias,
          int PC, int CNTP, int CNTD, int OFFP, int OFFD, int NPC)
{
    extern __shared__ char smem[];
    const uint32_t sbase = (uint32_t)__cvta_generic_to_shared(smem);
    const int tid  = threadIdx.x;
    const int lane = tid & 31, warp = tid >> 5;
    const int wm = (warp >> 2) * 64;             // 2 M-groups
    const int wn = (warp & 3) * 48;              // 4 N-groups of 48 (2 triples of 8 h-cols)
    const int col0 = blockIdx.x * FBN;
    const int prow0 = blockIdx.y * BM;           // parent logical row base
    const int KT = HFEAT / BK;                   // 4

    // A staging: 1024 chunks / 256 thr = 4
    const __half* asrc[4]; uint32_t adst[4];
    #pragma unroll
    for (int i = 0; i < 4; ++i) {
        int lin = tid + i * 256, r = lin >> 3, cc = lin & 7;
        int rr = prow0 + r;
        int t = rr / PC, lp = rr - t * PC;
        int gr = OFFP + t * CNTP + lp;
        asrc[i] = g_h16 + (size_t)gr * HFEAT + cc * 8;
        adst[i] = (uint32_t)((r * BKP + cc * 8) * 2);
    }
    // B staging: 192*8 = 1536 chunks / 256 thr = 6
    const __half* bsrc[6]; uint32_t bdst[6];
    #pragma unroll
    for (int i = 0; i < 6; ++i) {
        int lin = tid + i * 256, r = lin >> 3, cc = lin & 7;
        bsrc[i] = Whh + (size_t)(col0 + r) * HFEAT + cc * 8;
        bdst[i] = (uint32_t)((r * BKP + cc * 8) * 2);
    }
    auto issue = [&](int kt) {
        uint32_t sa = sbase + (uint32_t)(kt % NS) * FSTAGE;
        uint32_t sb = sa + A_STAGE_B;
        const int ko = kt * BK;
        #pragma unroll
        for (int i = 0; i < 4; ++i) cp16(sa + adst[i], asrc[i] + ko);
        #pragma unroll
        for (int i = 0; i < 6; ++i) cp16(sb + bdst[i], bsrc[i] + ko);
    };

    const int jb = lane >> 3, sub = lane & 7;
    uint32_t aoff[4], boff[3];
    #pragma unroll
    for (int mi = 0; mi < 4; ++mi) {
        int arow = wm + mi * 16 + (jb & 1) * 8 + sub;
        aoff[mi] = (uint32_t)(arow * BKP * 2 + (jb >> 1) * 16);
    }
    #pragma unroll
    for (int p = 0; p < 3; ++p) {
        int brow = wn + p * 16 + ((lane >> 4) & 1) * 8 + sub;
        boff[p] = (uint32_t)(brow * BKP * 2 + ((lane >> 3) & 1) * 16);
    }

    float acc[4][6][4];
    #pragma unroll
    for (int mi = 0; mi < 4; ++mi)
        #pragma unroll
        for (int ni = 0; ni < 6; ++ni)
            #pragma unroll
            for (int v = 0; v < 4; ++v) acc[mi][ni][v] = 0.f;

    #pragma unroll
    for (int s = 0; s < NS - 1; ++s) { issue(s); cp_commit(); }

    for (int kt = 0; kt < KT; ++kt) {
        cp_wait<NS - 2>();
        __syncthreads();
        int nk = kt + NS - 1;
        if (nk < KT) issue(nk);
        cp_commit();

        uint32_t sA = sbase + (uint32_t)(kt % NS) * FSTAGE;
        uint32_t sB = sA + A_STAGE_B;
        #pragma unroll
        for (int kk = 0; kk < BK / 16; ++kk) {
            const uint32_t kb = kk * 32;
            uint32_t afr[4][4], bfr[3][4];
            #pragma unroll
            for (int mi = 0; mi < 4; ++mi) ldsm4(afr[mi], sA + aoff[mi] + kb);
            #pragma unroll
            for (int p = 0; p < 3; ++p)   ldsm4(bfr[p], sB + boff[p] + kb);
            #pragma unroll
            for (int mi = 0; mi < 4; ++mi) {
                #pragma unroll
                for (int p = 0; p < 3; ++p) {
                    mma_f16(acc[mi][2 * p],     afr[mi], &bfr[p][0]);
                    mma_f16(acc[mi][2 * p + 1], afr[mi], &bfr[p][2]);
                }
            }
        }
        __syncthreads();
    }

    // ---- fused GRU epilogue: acc[mi][t3*3 + gate] are (r,z,n) triples ----
    const int quad = lane >> 2, tig = lane & 3;
    #pragma unroll
    for (int t3 = 0; t3 < 2; ++t3) {
        int cb = col0 + wn + t3 * 24 + 2 * tig;           // r column (2 cols)
        float2 br = *(const float2*)(bias + cb);
        float2 bz = *(const float2*)(bias + cb + 8);
        float2 bn = *(const float2*)(bias + cb + 16);
        int jj = ((col0 + wn) / 24 + t3) * 8 + 2 * tig;   // h column (2 cols)
        #pragma unroll
        for (int mi = 0; mi < 4; ++mi) {
            #pragma unroll
            for (int hh = 0; hh < 2; ++hh) {
                int grow = prow0 + wm + mi * 16 + quad + hh * 8;
                int t = grow / PC, lp = grow - t * PC;
                size_t prow  = (size_t)(OFFP + t * CNTP + lp);
                size_t crow0 = (size_t)(OFFD + t * CNTD + 3 * lp);
                float2 hp = *(const float2*)(g_h32 + prow * HFEAT + jj);
                float gr0 = acc[mi][t3 * 3 + 0][2 * hh]     + br.x;
                float gr1 = acc[mi][t3 * 3 + 0][2 * hh + 1] + br.y;
                float gz0 = acc[mi][t3 * 3 + 1][2 * hh]     + bz.x;
                float gz1 = acc[mi][t3 * 3 + 1][2 * hh + 1] + bz.y;
                float gn0 = acc[mi][t3 * 3 + 2][2 * hh]     + bn.x;
                float gn1 = acc[mi][t3 * 3 + 2][2 * hh + 1] + bn.y;
                #pragma unroll
                for (int k = 0; k < 3; ++k) {
                    size_t cr = crow0 + k;
                    const __half* gx = g_gx16 + cr * G3 + cb;
                    float2 xr = __half22float2(*(const __half2*)(gx));
                    float2 xz = __half22float2(*(const __half2*)(gx + 8));
                    float2 xn = __half22float2(*(const __half2*)(gx + 16));
                    float r0 = sigx(xr.x + gr0), r1 = sigx(xr.y + gr1);
                    float z0 = sigx(xz.x + gz0), z1 = sigx(xz.y + gz1);
                    float n0 = tanhx(xn.x + r0 * gn0), n1 = tanhx(xn.y + r1 * gn1);
                    float h0 = (1.0f - z0) * n0 + z0 * hp.x;
                    float h1 = (1.0f - z1) * n1 + z1 * hp.y;
                    *(float2*)(g_h32 + cr * HFEAT + jj) = make_float2(h0, h1);
                    if (3 * lp + k < NPC)
                        *(__half2*)(g_h16 + cr * HFEAT + jj) =
                            __floats2half2_rn(h0, h1);
                }
            }
        }
    }
}

// ---------------- misc kernels ------------------------------------------------
__global__ void f2h(const float* __restrict__ in, __half* __restrict__ out, int n8) {
    int i = blockIdx.x * 256 + threadIdx.x;
    if (i >= n8) return;
    const float4* p = (const float4*)in + i * 2;
    float4 v0 = p[0], v1 = p[1];
    __half2 h0 = __floats2half2_rn(v0.x, v0.y);
    __half2 h1 = __floats2half2_rn(v0.z, v0.w);
    __half2 h2 = __floats2half2_rn(v1.x, v1.y);
    __half2 h3 = __floats2half2_rn(v1.z, v1.w);
    uint4 u;
    u.x = *(uint32_t*)&h0; u.y = *(uint32_t*)&h1;
    u.z = *(uint32_t*)&h2; u.w = *(uint32_t*)&h3;
    *((uint4*)out + i) = u;
}

// weight convert with row permutation: dest row d <- src row gate*256 + j
__global__ void f2h_w_perm(const float* __restrict__ w, __half* __restrict__ o, int K) {
    int i = blockIdx.x * 256 + threadIdx.x;
    int cpr = K / 8;
    if (i >= G3 * cpr) return;
    int row = i / cpr, cc = i - row * cpr;
    int blk = row / 24, rem = row - blk * 24;
    int srow = (rem >> 3) * HFEAT + blk * 8 + (rem & 7);
    const float4* p = (const float4*)(w + (size_t)srow * K) + cc * 2;
    float4 v0 = p[0], v1 = p[1];
    __half2 h0 = __floats2half2_rn(v0.x, v0.y);
    __half2 h1 = __floats2half2_rn(v0.z, v0.w);
    __half2 h2 = __floats2half2_rn(v1.x, v1.y);
    __half2 h3 = __floats2half2_rn(v1.z, v1.w);
    uint4 u;
    u.x = *(uint32_t*)&h0; u.y = *(uint32_t*)&h1;
    u.z = *(uint32_t*)&h2; u.w = *(uint32_t*)&h3;
    *((uint4*)(o + (size_t)row * K) + cc) = u;
}

__global__ void perm_bias(const float* __restrict__ b, float* __restrict__ o) {
    int row = blockIdx.x * 256 + threadIdx.x;
    if (row >= G3) return;
    int blk = row / 24, rem = row - blk * 24;
    o[row] = b[(rem >> 3) * HFEAT + blk * 8 + (rem & 7)];
}

__global__ void ew_level0(const float* __restrict__ b_hh) {
    int t = blockIdx.x, j = threadIdx.x;
    const __half* gx = g_gx16 + (size_t)t * G3;           // level-major row t
    int base = (j >> 3) * 24 + (j & 7);                   // interleaved cols
    float xr = __half2float(gx[base]);
    float xz = __half2float(gx[base + 8]);
    float xn = __half2float(gx[base + 16]);
    float r = sigx(xr + b_hh[j]);
    float z = sigx(xz + b_hh[HFEAT + j]);
    float n = tanhx(xn + r * b_hh[2 * HFEAT + j]);
    float h = (1.0f - z) * n;
    g_h32[(size_t)t * HFEAT + j] = h;
    g_h16[(size_t)t * HFEAT + j] = __float2half_rn(h);
}

__global__ void leaf_max(float* __restrict__ out) {
    int t = blockIdx.x, j = threadIdx.x;
    float m = -3.402823466e+38f;
    const float* h5 = g_h32 + (size_t)(61952 + t * 243) * HFEAT;
    #pragma unroll 4
    for (int ls = 12; ls < 243; ++ls) m = fmaxf(m, h5[(size_t)ls * HFEAT + j]);
    const float* h6 = g_h32 + (size_t)(186368 + t * 36) * HFEAT;
    #pragma unroll 4
    for (int ls = 0; ls < 36; ++ls)   m = fmaxf(m, h6[(size_t)ls * HFEAT + j]);
    out[(size_t)t * HFEAT + j] = m;
}

// ---------------- launch -------------------------------------------------------
extern "C" void kernel_launch(void* const* d_in, const int* in_sizes, int n_in,
                              void* d_out, int out_size) {
    const float* inputs = (const float*)d_in[0];
    const float* W_ih   = (const float*)d_in[1];
    const float* W_hh   = (const float*)d_in[2];
    const float* b_ih   = (const float*)d_in[3];
    const float* b_hh   = (const float*)d_in[4];
    float* out = (float*)d_out;

    __half *p_gx16, *p_x16, *p_wih, *p_whh;
    float *p_bihp, *p_bhhp;
    cudaGetSymbolAddress((void**)&p_gx16, g_gx16);
    cudaGetSymbolAddress((void**)&p_x16,  g_x16);
    cudaGetSymbolAddress((void**)&p_wih,  g_wih);
    cudaGetSymbolAddress((void**)&p_whh,  g_whh);
    cudaGetSymbolAddress((void**)&p_bihp, g_bihp);
    cudaGetSymbolAddress((void**)&p_bhhp, g_bhhp);

    cudaFuncSetAttribute(gemm_gx,
                         cudaFuncAttributeMaxDynamicSharedMemorySize, SMEM_GX);
    cudaFuncSetAttribute(gru_fused,
                         cudaFuncAttributeMaxDynamicSharedMemorySize, SMEM_FU);

    static const int cnt[7]   = {1, 3, 9, 27, 81, 243, 36};
    static const int off[7]   = {0, 512, 2048, 6656, 20480, 61952, 186368};
    static const int PC[8]    = {0, 1, 3, 9, 27, 81, 12, 0};

    // 0) conversions: weights permuted, biases permuted, inputs plain
    f2h_w_perm<<<(G3 * (INFEAT / 8) + 255) / 256, 256>>>(W_ih, p_wih, INFEAT);
    f2h_w_perm<<<(G3 * (HFEAT / 8) + 255) / 256, 256>>>(W_hh, p_whh, HFEAT);
    perm_bias<<<3, 256>>>(b_ih, p_bihp);
    perm_bias<<<3, 256>>>(b_hh, p_bhhp);
    f2h<<<(NNODES * INFEAT / 8 + 255) / 256, 256>>>(inputs, p_x16, NNODES * INFEAT / 8);

    // 1) gx = inputs @ W_ih'^T + b_ih'  (level-major rows, interleaved cols)
    gemm_gx<<<dim3(G3 / BN, NNODES / BM), NTHR, SMEM_GX>>>(
        p_x16, p_wih, p_bihp, p_gx16);

    // 2) roots
    ew_level0<<<TREES, 256>>>(b_hh);

    // 3) levels 1..6: fused gh-GEMM + GRU
    for (int d = 1; d < 7; ++d) {
        int M = PC[d] * TREES;
        gru_fused<<<dim3(G3 / FBN, M / BM), 256, SMEM_FU>>>(
            p_whh, p_bhhp, PC[d], cnt[d - 1], cnt[d],
            off[d - 1], off[d], PC[d + 1]);
    }

    // 4) leaf max
    leaf_max<<<TREES, 256>>>(out);

    (void)in_sizes; (void)n_in; (void)out_size;
}

// round 15
// speedup vs baseline: 1.4231x; 1.4231x over previous
#include <cuda_runtime.h>
#include <cuda_fp16.h>
#include <cstdint>

// ---------------- problem constants ----------------------------------------
#define TREES   512
#define TSIZE   400
#define NNODES  (TREES * TSIZE)   // 204800
#define INFEAT  768
#define HFEAT   256
#define G3      768

// level geometry (ternary tree, 400 nodes):
//  d:      0    1    2    3     4     5      6
//  cnt:    1    3    9    27    81    243    36
//  start:  0    1    4    13    40    121    364
//  level-major row offsets: 0 512 2048 6656 20480 61952 186368  (end 204800)
//  parents for level d = first PC[d] locals of level d-1; PC: 1 3 9 27 81 12
//  leaves: level-5 locals 12..242 + all level-6

// ---------------- scratch (device bss) ---------------------------------------
__device__ __half g_gx16[(size_t)NNODES * G3];         // input gates fp16, LEVEL-major
__device__ __half g_h16 [(size_t)NNODES * HFEAT];      // hiddens fp16, level-major
__device__ __half g_gh16[(size_t)(81 * TREES) * G3];   // parent gates fp16
__device__ __half g_x16 [(size_t)NNODES * INFEAT];     // fp16 inputs (node-major)
__device__ __half g_wih [3 * HFEAT * INFEAT];          // fp16 W_ih
__device__ __half g_whh [3 * HFEAT * HFEAT];           // fp16 W_hh

// level-major row -> node row (node = tree*400 + s)
__device__ __forceinline__ int lm2node(int r) {
    int o, c, s0;
    if (r < 20480) {
        if (r < 2048) { if (r < 512) { o = 0;     c = 1;  s0 = 0;  }
                        else         { o = 512;   c = 3;  s0 = 1;  } }
        else          { if (r < 6656){ o = 2048;  c = 9;  s0 = 4;  }
                        else         { o = 6656;  c = 27; s0 = 13; } }
    } else {
        if (r < 186368){ if (r < 61952){ o = 20480; c = 81;  s0 = 40;  }
                         else          { o = 61952; c = 243; s0 = 121; } }
        else           { o = 186368; c = 36; s0 = 364; }
    }
    int t = (r - o) / c;
    int ls = (r - o) - t * c;
    return t * TSIZE + s0 + ls;
}

// ---------------- PTX helpers ------------------------------------------------
__device__ __forceinline__ void mma_f16(float* c, const uint32_t* a, const uint32_t* b) {
    asm volatile(
        "mma.sync.aligned.m16n8k16.row.col.f32.f16.f16.f32 "
        "{%0,%1,%2,%3}, {%4,%5,%6,%7}, {%8,%9}, {%0,%1,%2,%3};"
        : "+f"(c[0]), "+f"(c[1]), "+f"(c[2]), "+f"(c[3])
        : "r"(a[0]), "r"(a[1]), "r"(a[2]), "r"(a[3]), "r"(b[0]), "r"(b[1]));
}
__device__ __forceinline__ void ldsm4(uint32_t* r, uint32_t saddr) {
    asm volatile("ldmatrix.sync.aligned.m8n8.x4.shared.b16 {%0,%1,%2,%3}, [%4];"
        : "=r"(r[0]), "=r"(r[1]), "=r"(r[2]), "=r"(r[3]) : "r"(saddr));
}
__device__ __forceinline__ void cp16(uint32_t saddr, const void* g) {
    asm volatile("cp.async.cg.shared.global [%0], [%1], 16;" :: "r"(saddr), "l"(g));
}
__device__ __forceinline__ void cp_commit() { asm volatile("cp.async.commit_group;"); }
template <int N> __device__ __forceinline__ void cp_wait() {
    asm volatile("cp.async.wait_group %0;" :: "n"(N));
}

// fast accurate sigmoid/tanh: ex2.approx + rcp.approx (~1e-6 rel err)
__device__ __forceinline__ float sigx(float x) {
    float e, r;
    asm("ex2.approx.f32 %0, %1;" : "=f"(e) : "f"(-x * 1.4426950408889634f));
    asm("rcp.approx.f32 %0, %1;" : "=f"(r) : "f"(1.0f + e));
    return r;
}
__device__ __forceinline__ float tanhx(float x) {
    float e, r;
    asm("ex2.approx.f32 %0, %1;" : "=f"(e) : "f"(-x * 2.8853900817779268f));
    asm("rcp.approx.f32 %0, %1;" : "=f"(r) : "f"(1.0f + e));
    return __fmaf_rn(2.0f, r, -1.0f);
}

// ================= fp16 GEMM: C16[M,768] = A16[M,KDIM]*B16^T + bias ==========
// R8 config: BM=BN=128, BK=64, NS=3, 256 threads, 2 CTAs/SM.
// GMODE 1: parent-subset gather  (row r -> (r/PC)*STR + r%PC)
// GMODE 2: level-major gather    (row r -> lm2node(r))
#define BM 128
#define BN 128
#define BK 64
#define NS 3
#define BKP 72
#define A_STAGE_B (BM * BKP * 2)                 // 18432
#define B_STAGE_B (BN * BKP * 2)                 // 18432
#define STAGE_B   (A_STAGE_B + B_STAGE_B)        // 36864
#define SMEM_GX   (NS * STAGE_B)                 // 110592
#define NTHR 256

template <int KDIM, int GMODE>
__global__ void __launch_bounds__(NTHR, 2)
gemm_h(const __half* __restrict__ A, const __half* __restrict__ B,
       const float* __restrict__ bias, __half* __restrict__ C,
       int PC, int STR)
{
    extern __shared__ char smem[];
    const uint32_t sbase = (uint32_t)__cvta_generic_to_shared(smem);
    const int tid  = threadIdx.x;
    const int lane = tid & 31, warp = tid >> 5;
    const int wm = (warp >> 2) * 64;             // 2 warp-groups along M
    const int wn = (warp & 3) * 32;              // 4 along N
    const int col0 = blockIdx.x * BN;
    const int row0 = blockIdx.y * BM;
    const int KT = KDIM / BK;

    const __half* asrc[4]; uint32_t adst[4];
    #pragma unroll
    for (int i = 0; i < 4; ++i) {
        int lin = tid + i * NTHR, r = lin >> 3, cc = lin & 7;
        int rr = row0 + r, gr;
        if (GMODE == 1)      { int t = rr / PC; gr = t * STR + (rr - t * PC); }
        else                 { gr = lm2node(rr); }
        asrc[i] = A + (size_t)gr * KDIM + cc * 8;
        adst[i] = (uint32_t)((r * BKP + cc * 8) * 2);
    }
    const __half* bsrc[4]; uint32_t bdst[4];
    #pragma unroll
    for (int i = 0; i < 4; ++i) {
        int lin = tid + i * NTHR, r = lin >> 3, cc = lin & 7;
        bsrc[i] = B + (size_t)(col0 + r) * KDIM + cc * 8;
        bdst[i] = (uint32_t)((r * BKP + cc * 8) * 2);
    }
    auto issue = [&](int kt) {
        uint32_t sa = sbase + (uint32_t)(kt % NS) * STAGE_B;
        uint32_t sb = sa + A_STAGE_B;
        const int ko = kt * BK;
        #pragma unroll
        for (int i = 0; i < 4; ++i) cp16(sa + adst[i], asrc[i] + ko);
        #pragma unroll
        for (int i = 0; i < 4; ++i) cp16(sb + bdst[i], bsrc[i] + ko);
    };

    const int j = lane >> 3, sub = lane & 7;
    uint32_t aoff[4], boff[2];
    #pragma unroll
    for (int mi = 0; mi < 4; ++mi) {
        int arow = wm + mi * 16 + (j & 1) * 8 + sub;
        aoff[mi] = (uint32_t)(arow * BKP * 2 + (j >> 1) * 16);
    }
    #pragma unroll
    for (int p = 0; p < 2; ++p) {
        int brow = wn + p * 16 + ((lane >> 4) & 1) * 8 + sub;
        boff[p] = (uint32_t)(brow * BKP * 2 + ((lane >> 3) & 1) * 16);
    }

    float acc[4][4][4];
    #pragma unroll
    for (int mi = 0; mi < 4; ++mi)
        #pragma unroll
        for (int ni = 0; ni < 4; ++ni)
            #pragma unroll
            for (int v = 0; v < 4; ++v) acc[mi][ni][v] = 0.f;

    #pragma unroll
    for (int s = 0; s < NS - 1; ++s) { issue(s); cp_commit(); }

    for (int kt = 0; kt < KT; ++kt) {
        cp_wait<NS - 2>();
        __syncthreads();
        int nk = kt + NS - 1;
        if (nk < KT) issue(nk);
        cp_commit();

        uint32_t sA = sbase + (uint32_t)(kt % NS) * STAGE_B;
        uint32_t sB = sA + A_STAGE_B;
        #pragma unroll
        for (int kk = 0; kk < BK / 16; ++kk) {
            const uint32_t kb = kk * 32;
            uint32_t afr[4][4], bfr[2][4];
            #pragma unroll
            for (int mi = 0; mi < 4; ++mi) ldsm4(afr[mi], sA + aoff[mi] + kb);
            #pragma unroll
            for (int p = 0; p < 2; ++p)   ldsm4(bfr[p], sB + boff[p] + kb);
            #pragma unroll
            for (int mi = 0; mi < 4; ++mi) {
                #pragma unroll
                for (int p = 0; p < 2; ++p) {
                    mma_f16(acc[mi][2 * p],     afr[mi], &bfr[p][0]);
                    mma_f16(acc[mi][2 * p + 1], afr[mi], &bfr[p][2]);
                }
            }
        }
        __syncthreads();
    }

    // epilogue: bias fp32, store fp16
    const int g = lane >> 2, tig = lane & 3;
    #pragma unroll
    for (int mi = 0; mi < 4; ++mi) {
        int row = row0 + wm + mi * 16 + g;
        #pragma unroll
        for (int ni = 0; ni < 4; ++ni) {
            int col = col0 + wn + ni * 8 + 2 * tig;
            float b0 = bias[col], b1 = bias[col + 1];
            *(__half2*)(C + (size_t)row * G3 + col) =
                __floats2half2_rn(acc[mi][ni][0] + b0, acc[mi][ni][1] + b1);
            *(__half2*)(C + (size_t)(row + 8) * G3 + col) =
                __floats2half2_rn(acc[mi][ni][2] + b0, acc[mi][ni][3] + b1);
        }
    }
}

// ---------------- misc kernels ------------------------------------------------
__global__ void f2h(const float* __restrict__ in, __half* __restrict__ out, int n8) {
    int i = blockIdx.x * 256 + threadIdx.x;
    if (i >= n8) return;
    const float4* p = (const float4*)in + i * 2;
    float4 v0 = p[0], v1 = p[1];
    __half2 h0 = __floats2half2_rn(v0.x, v0.y);
    __half2 h1 = __floats2half2_rn(v0.z, v0.w);
    __half2 h2 = __floats2half2_rn(v1.x, v1.y);
    __half2 h3 = __floats2half2_rn(v1.z, v1.w);
    uint4 u;
    u.x = *(uint32_t*)&h0; u.y = *(uint32_t*)&h1;
    u.z = *(uint32_t*)&h2; u.w = *(uint32_t*)&h3;
    *((uint4*)out + i) = u;
}

// roots: h = (1-z)*n ; 128 threads, 2 cols/thread
__global__ void ew_level0(const float* __restrict__ b_hh) {
    int t = blockIdx.x, j2 = threadIdx.x;                 // j = 2*j2, 2*j2+1
    const __half* gx = g_gx16 + (size_t)t * G3;           // level-major row t
    float2 xr = __half22float2(*(const __half2*)(gx + 2 * j2));
    float2 xz = __half22float2(*(const __half2*)(gx + HFEAT + 2 * j2));
    float2 xn = __half22float2(*(const __half2*)(gx + 2 * HFEAT + 2 * j2));
    float2 br = *(const float2*)(b_hh + 2 * j2);
    float2 bz = *(const float2*)(b_hh + HFEAT + 2 * j2);
    float2 bn = *(const float2*)(b_hh + 2 * HFEAT + 2 * j2);
    float r0 = sigx(xr.x + br.x), r1 = sigx(xr.y + br.y);
    float z0 = sigx(xz.x + bz.x), z1 = sigx(xz.y + bz.y);
    float n0 = tanhx(xn.x + r0 * bn.x), n1 = tanhx(xn.y + r1 * bn.y);
    *(__half2*)(g_h16 + (size_t)t * HFEAT + 2 * j2) =
        __floats2half2_rn((1.0f - z0) * n0, (1.0f - z1) * n1);
}

// level d>=1: gh16 (bias fused) from parent-subset GEMM; 128 threads, half2
__global__ void ew_level(int cnt_d, int cnt_p, int start_d, int start_p,
                         int off_d, int off_p, int PC) {
    int p = blockIdx.x, j2 = threadIdx.x;                 // row p, cols 2*j2..+1
    int t = p / cnt_d;
    int ls = p - t * cnt_d;                               // local child idx
    int lp = (start_d + ls - 1) / 3 - start_p;            // parent local idx
    int ghrow = t * PC + lp;
    int hrow  = off_p + t * cnt_p + lp;
    int drow  = off_d + p;
    float2 hp = __half22float2(*(const __half2*)(g_h16 + (size_t)hrow * HFEAT + 2 * j2));
    const __half* gx = g_gx16 + (size_t)drow * G3;
    const __half* gh = g_gh16 + (size_t)ghrow * G3;
    float2 xr = __half22float2(*(const __half2*)(gx + 2 * j2));
    float2 xz = __half22float2(*(const __half2*)(gx + HFEAT + 2 * j2));
    float2 xn = __half22float2(*(const __half2*)(gx + 2 * HFEAT + 2 * j2));
    float2 gr = __half22float2(*(const __half2*)(gh + 2 * j2));
    float2 gz = __half22float2(*(const __half2*)(gh + HFEAT + 2 * j2));
    float2 gn = __half22float2(*(const __half2*)(gh + 2 * HFEAT + 2 * j2));
    float r0 = sigx(xr.x + gr.x), r1 = sigx(xr.y + gr.y);
    float z0 = sigx(xz.x + gz.x), z1 = sigx(xz.y + gz.y);
    float n0 = tanhx(xn.x + r0 * gn.x), n1 = tanhx(xn.y + r1 * gn.y);
    float h0 = (1.0f - z0) * n0 + z0 * hp.x;
    float h1 = (1.0f - z1) * n1 + z1 * hp.y;
    *(__half2*)(g_h16 + (size_t)drow * HFEAT + 2 * j2) = __floats2half2_rn(h0, h1);
}

// per-tree leaf max over fp16 hiddens; 128 threads, 2 cols/thread
__global__ void leaf_max(float* __restrict__ out) {
    int t = blockIdx.x, j2 = threadIdx.x;
    float m0 = -3.402823466e+38f, m1 = m0;
    const __half* h5 = g_h16 + (size_t)(61952 + t * 243) * HFEAT + 2 * j2;
    #pragma unroll 4
    for (int ls = 12; ls < 243; ++ls) {
        float2 v = __half22float2(*(const __half2*)(h5 + (size_t)ls * HFEAT));
        m0 = fmaxf(m0, v.x); m1 = fmaxf(m1, v.y);
    }
    const __half* h6 = g_h16 + (size_t)(186368 + t * 36) * HFEAT + 2 * j2;
    #pragma unroll 4
    for (int ls = 0; ls < 36; ++ls) {
        float2 v = __half22float2(*(const __half2*)(h6 + (size_t)ls * HFEAT));
        m0 = fmaxf(m0, v.x); m1 = fmaxf(m1, v.y);
    }
    *(float2*)(out + (size_t)t * HFEAT + 2 * j2) = make_float2(m0, m1);
}

// ---------------- launch -------------------------------------------------------
extern "C" void kernel_launch(void* const* d_in, const int* in_sizes, int n_in,
                              void* d_out, int out_size) {
    const float* inputs = (const float*)d_in[0];
    const float* W_ih   = (const float*)d_in[1];
    const float* W_hh   = (const float*)d_in[2];
    const float* b_ih   = (const float*)d_in[3];
    const float* b_hh   = (const float*)d_in[4];
    float* out = (float*)d_out;

    __half *p_gx16, *p_gh16, *p_x16, *p_wih, *p_whh, *p_h16;
    cudaGetSymbolAddress((void**)&p_gx16, g_gx16);
    cudaGetSymbolAddress((void**)&p_gh16, g_gh16);
    cudaGetSymbolAddress((void**)&p_x16,  g_x16);
    cudaGetSymbolAddress((void**)&p_wih,  g_wih);
    cudaGetSymbolAddress((void**)&p_whh,  g_whh);
    cudaGetSymbolAddress((void**)&p_h16,  g_h16);

    cudaFuncSetAttribute(gemm_h<INFEAT, 2>,
                         cudaFuncAttributeMaxDynamicSharedMemorySize, SMEM_GX);
    cudaFuncSetAttribute(gemm_h<HFEAT, 1>,
                         cudaFuncAttributeMaxDynamicSharedMemorySize, SMEM_GX);

    static const int cnt[7]   = {1, 3, 9, 27, 81, 243, 36};
    static const int start[7] = {0, 1, 4, 13, 40, 121, 364};
    static const int off[7]   = {0, 512, 2048, 6656, 20480, 61952, 186368};
    static const int PC[7]    = {0, 1, 3, 9, 27, 81, 12};

    // 0) fp16 conversions
    f2h<<<(NNODES * INFEAT / 8 + 255) / 256, 256>>>(inputs, p_x16, NNODES * INFEAT / 8);
    f2h<<<(3 * HFEAT * INFEAT / 8 + 255) / 256, 256>>>(W_ih, p_wih, 3 * HFEAT * INFEAT / 8);
    f2h<<<(3 * HFEAT * HFEAT / 8 + 255) / 256, 256>>>(W_hh, p_whh, 3 * HFEAT * HFEAT / 8);

    // 1) gx = inputs @ W_ih^T + b_ih  (fp16 out, level-major rows)
    gemm_h<INFEAT, 2><<<dim3(G3 / BN, NNODES / BM), NTHR, SMEM_GX>>>(
        p_x16, p_wih, b_ih, p_gx16, 0, 0);

    // 2) roots
    ew_level0<<<TREES, 128>>>(b_hh);

    // 3) levels 1..6: parent-subset gh GEMM (fp16 out, bias fused) + GRU ew
    for (int d = 1; d < 7; ++d) {
        int M = PC[d] * TREES;
        gemm_h<HFEAT, 1><<<dim3(G3 / BN, M / BM), NTHR, SMEM_GX>>>(
            p_h16 + (size_t)off[d - 1] * HFEAT, p_whh, b_hh, p_gh16,
            PC[d], cnt[d - 1]);
        ew_level<<<cnt[d] * TREES, 128>>>(cnt[d], cnt[d - 1], start[d], start[d - 1],
                                          off[d], off[d - 1], PC[d]);
    }

    // 4) leaf max
    leaf_max<<<TREES, 128>>>(out);

    (void)in_sizes; (void)n_in; (void)out_size;
}